// round 16
// baseline (speedup 1.0000x reference)
#include <cuda_runtime.h>
#include <cuda_bf16.h>
#include <cstdint>

// Problem: B=8, L=256, Z=16, H=256. Reassociated (12.9 GFLOP):
//   A: Wc[bz][i][j] = sum_o cls[bz][o] * W[i][o][j]
//   B: t[b][x*16+z][j] = sum_i start[b][x][i] * Wc[bz][i][j]
//   C: out[b][x][y][z] = sum_j t[b][m][j] * end[b][y][j]
// bf16 mma.sync m16n8k16, 3-term split. R16: kernB/kernC use 128-thread CTAs
// with 64x64 tiles -> ~6 CTAs/SM (24 warps/SM vs 16) to attack HMMA latency
// hiding. kernA stays 256-thread / 128x128 (R11/R15 form).

typedef unsigned u32;
typedef unsigned long long u64;

__device__ u32 g_clsh[16384],   g_clsl[16384];    // cls  [bz=128][op=128]
__device__ u32 g_sth[262144],   g_stl[262144];    // start[b*x=2048][ip=128]
__device__ u32 g_endh[262144],  g_endl[262144];   // end  [b*y=2048][jp=128]
__device__ float g_wc[8388608];                   // Wc   [bz][i][j] fp32
__device__ u32 g_wcth[4194304], g_wctl[4194304];  // Wc^T [bz][j=256][ip=128]
__device__ u32 g_th[4194304],   g_tl[4194304];    // t    [b*m=32768][jp=128]

// ---------------- bf16 helpers --------------------------------------------
__device__ __forceinline__ u32 packbf(__nv_bfloat16 e0, __nv_bfloat16 e1) {
    return ((u32)__bfloat16_as_ushort(e1) << 16) | (u32)__bfloat16_as_ushort(e0);
}
__device__ __forceinline__ u32 packsplit(float f0, float f1, u32& lo) {
    __nv_bfloat16 h0 = __float2bfloat16_rn(f0), h1 = __float2bfloat16_rn(f1);
    float r0 = f0 - __bfloat162float(h0), r1 = f1 - __bfloat162float(h1);
    lo = packbf(__float2bfloat16_rn(r0), __float2bfloat16_rn(r1));
    return packbf(h0, h1);
}
__device__ __forceinline__ void mma_bf16(float d[4], u32 a0, u32 a1, u32 a2, u32 a3,
                                         u32 b0, u32 b1)
{
    asm("mma.sync.aligned.m16n8k16.row.col.f32.bf16.bf16.f32 "
        "{%0,%1,%2,%3}, {%4,%5,%6,%7}, {%8,%9}, {%0,%1,%2,%3};"
        : "+f"(d[0]), "+f"(d[1]), "+f"(d[2]), "+f"(d[3])
        : "r"(a0), "r"(a1), "r"(a2), "r"(a3), "r"(b0), "r"(b1));
}

#define PAD 136   // 128-wide tiles (kernA)
#define PADS 72   // 64-wide tiles (kernB/C); 72 % 32 == 8 -> conflict-free

// ---------------- 128x128-tile phase (kernA; 8 warps, wn 2x64) -------------
__device__ __forceinline__ void mma_phase128(const u32 (*AsH)[PAD], const u32 (*AsL)[PAD],
                                             const u32 (*WsH)[PAD], const u32 (*WsL)[PAD],
                                             int lane, int wm, int wn, float acc[2][8][4])
{
    int fr = lane >> 2, fk = lane & 3;
    u32 ah[2][4], al[2][4];
#pragma unroll
    for (int mb = 0; mb < 2; mb++) {
        int m = wm + mb * 16 + fr;
        ah[mb][0] = AsH[fk][m];     ah[mb][1] = AsH[fk][m + 8];
        ah[mb][2] = AsH[fk + 4][m]; ah[mb][3] = AsH[fk + 4][m + 8];
        al[mb][0] = AsL[fk][m];     al[mb][1] = AsL[fk][m + 8];
        al[mb][2] = AsL[fk + 4][m]; al[mb][3] = AsL[fk + 4][m + 8];
    }
#pragma unroll
    for (int g = 0; g < 2; g++) {
        u32 bh0[4], bh1[4], bl0[4], bl1[4];
#pragma unroll
        for (int q = 0; q < 4; q++) {
            int n = wn + (g * 4 + q) * 8 + fr;
            bh0[q] = WsH[fk][n]; bh1[q] = WsH[fk + 4][n];
            bl0[q] = WsL[fk][n]; bl1[q] = WsL[fk + 4][n];
        }
#pragma unroll
        for (int q = 0; q < 4; q++)
#pragma unroll
            for (int mb = 0; mb < 2; mb++)
                mma_bf16(acc[mb][g * 4 + q], ah[mb][0], ah[mb][1], ah[mb][2], ah[mb][3],
                         bh0[q], bh1[q]);
#pragma unroll
        for (int q = 0; q < 4; q++)
#pragma unroll
            for (int mb = 0; mb < 2; mb++)
                mma_bf16(acc[mb][g * 4 + q], ah[mb][0], ah[mb][1], ah[mb][2], ah[mb][3],
                         bl0[q], bl1[q]);
#pragma unroll
        for (int q = 0; q < 4; q++)
#pragma unroll
            for (int mb = 0; mb < 2; mb++)
                mma_bf16(acc[mb][g * 4 + q], al[mb][0], al[mb][1], al[mb][2], al[mb][3],
                         bh0[q], bh1[q]);
    }
}

// ---------------- 64x64-tile phase (kernB/C; 4 warps, 32x32 warp tiles) ----
__device__ __forceinline__ void mma_phase64(const u32 (*AsH)[PADS], const u32 (*AsL)[PADS],
                                            const u32 (*WsH)[PADS], const u32 (*WsL)[PADS],
                                            int lane, int wm, int wn, float acc[2][4][4])
{
    int fr = lane >> 2, fk = lane & 3;
    u32 ah[2][4], al[2][4];
#pragma unroll
    for (int mb = 0; mb < 2; mb++) {
        int m = wm + mb * 16 + fr;
        ah[mb][0] = AsH[fk][m];     ah[mb][1] = AsH[fk][m + 8];
        ah[mb][2] = AsH[fk + 4][m]; ah[mb][3] = AsH[fk + 4][m + 8];
        al[mb][0] = AsL[fk][m];     al[mb][1] = AsL[fk][m + 8];
        al[mb][2] = AsL[fk + 4][m]; al[mb][3] = AsL[fk + 4][m + 8];
    }
    u32 bh0[4], bh1[4], bl0[4], bl1[4];
#pragma unroll
    for (int q = 0; q < 4; q++) {
        int n = wn + q * 8 + fr;
        bh0[q] = WsH[fk][n]; bh1[q] = WsH[fk + 4][n];
        bl0[q] = WsL[fk][n]; bl1[q] = WsL[fk + 4][n];
    }
#pragma unroll
    for (int q = 0; q < 4; q++)
#pragma unroll
        for (int mb = 0; mb < 2; mb++)
            mma_bf16(acc[mb][q], ah[mb][0], ah[mb][1], ah[mb][2], ah[mb][3], bh0[q], bh1[q]);
#pragma unroll
    for (int q = 0; q < 4; q++)
#pragma unroll
        for (int mb = 0; mb < 2; mb++)
            mma_bf16(acc[mb][q], ah[mb][0], ah[mb][1], ah[mb][2], ah[mb][3], bl0[q], bl1[q]);
#pragma unroll
    for (int q = 0; q < 4; q++)
#pragma unroll
        for (int mb = 0; mb < 2; mb++)
            mma_bf16(acc[mb][q], al[mb][0], al[mb][1], al[mb][2], al[mb][3], bh0[q], bh1[q]);
}

// --------------------------- input split prepass ---------------------------
__global__ void split_inputs(const float* __restrict__ cls,
                             const float* __restrict__ start,
                             const float* __restrict__ endl)
{
    long p = (long)blockIdx.x * 256 + threadIdx.x;
    const float* src; u32 *dh, *dl; long off;
    if (p < 16384)              { src = cls;   dh = g_clsh; dl = g_clsl; off = p; }
    else if (p < 16384 + 262144){ src = start; dh = g_sth;  dl = g_stl;  off = p - 16384; }
    else if (p < 16384 + 524288){ src = endl;  dh = g_endh; dl = g_endl; off = p - 16384 - 262144; }
    else return;
    float f0 = src[off * 2], f1 = src[off * 2 + 1];
    u32 lo; u32 hi = packsplit(f0, f1, lo);
    dh[off] = hi; dl[off] = lo;
}

// ---------------------------------------------------------------------------
// kernA: per (j-half, i): Wc[bz=128][j=128] over K=o=256 (16 chunks of k16).
// ---------------------------------------------------------------------------
__global__ __launch_bounds__(256, 2)
void kernA_mma(const float* __restrict__ W)
{
    __shared__ u32 AsH[8][PAD], AsL[8][PAD], WsH[8][PAD], WsL[8][PAD];
    int tid = threadIdx.x, lane = tid & 31, wid = tid >> 5;
    int j0 = blockIdx.x * 128, i_dim = blockIdx.z;
    int wm = (wid & 3) * 32, wn = (wid >> 2) * 64;
    const float* Wi = W + (long)i_dim * 65536;   // [o=256][j=256]

    float acc[2][8][4];
#pragma unroll
    for (int mb = 0; mb < 2; mb++)
#pragma unroll
        for (int nb = 0; nb < 8; nb++)
#pragma unroll
            for (int q = 0; q < 4; q++) acc[mb][nb][q] = 0.f;

    int kp = tid >> 5;
    int j4 = (tid & 31) * 4;
    int cm = tid >> 1, ckq = (tid & 1) * 4;

    float4 w0 = *(const float4*)(Wi + (long)(2 * kp) * 256 + j0 + j4);
    float4 w1 = *(const float4*)(Wi + (long)(2 * kp + 1) * 256 + j0 + j4);
    uint4 vh = *(const uint4*)(g_clsh + (long)cm * 128 + ckq);
    uint4 vl = *(const uint4*)(g_clsl + (long)cm * 128 + ckq);

    for (int c = 0; c < 16; c++) {
        {
            float e0[4] = {w0.x, w0.y, w0.z, w0.w};
            float e1[4] = {w1.x, w1.y, w1.z, w1.w};
            u32 hh[4], ll[4];
#pragma unroll
            for (int e = 0; e < 4; e++) hh[e] = packsplit(e0[e], e1[e], ll[e]);
            *(uint4*)&WsH[kp][j4] = make_uint4(hh[0], hh[1], hh[2], hh[3]);
            *(uint4*)&WsL[kp][j4] = make_uint4(ll[0], ll[1], ll[2], ll[3]);
            AsH[ckq + 0][cm] = vh.x; AsH[ckq + 1][cm] = vh.y;
            AsH[ckq + 2][cm] = vh.z; AsH[ckq + 3][cm] = vh.w;
            AsL[ckq + 0][cm] = vl.x; AsL[ckq + 1][cm] = vl.y;
            AsL[ckq + 2][cm] = vl.z; AsL[ckq + 3][cm] = vl.w;
        }
        __syncthreads();
        if (c + 1 < 16) {
            int o1 = (c + 1) * 16, kp1 = (c + 1) * 8;
            w0 = *(const float4*)(Wi + (long)(o1 + 2 * kp) * 256 + j0 + j4);
            w1 = *(const float4*)(Wi + (long)(o1 + 2 * kp + 1) * 256 + j0 + j4);
            vh = *(const uint4*)(g_clsh + (long)cm * 128 + kp1 + ckq);
            vl = *(const uint4*)(g_clsl + (long)cm * 128 + kp1 + ckq);
        }
        mma_phase128(AsH, AsL, WsH, WsL, lane, wm, wn, acc);
        __syncthreads();
    }

    int fr = lane >> 2, fc = (lane & 3) * 2;
#pragma unroll
    for (int mb = 0; mb < 2; mb++) {
#pragma unroll
        for (int nb = 0; nb < 8; nb++) {
            long m = wm + mb * 16 + fr;
            long j = j0 + wn + nb * 8 + fc;
            float* p0 = g_wc + m * 65536 + (long)i_dim * 256 + j;
            float* p1 = p0 + 8 * 65536;
            *(float2*)p0 = make_float2(acc[mb][nb][0], acc[mb][nb][1]);
            *(float2*)p1 = make_float2(acc[mb][nb][2], acc[mb][nb][3]);
        }
    }
}

// ---------------------------------------------------------------------------
// repack: Wc fp32 [bz][i][j] -> Wc^T packed bf16 pairs [bz][j][ip=128] hi/lo.
// ---------------------------------------------------------------------------
__global__ void repack_wc()
{
    __shared__ float T[32][33];
    int bz = blockIdx.z, i0 = blockIdx.y * 32, j0 = blockIdx.x * 32;
    const float* src = g_wc + (long)bz * 65536;
    int t = threadIdx.x;
    int jj = t & 31, g = t >> 5;
#pragma unroll
    for (int rr = 0; rr < 4; rr++) {
        int ii = g * 4 + rr;
        T[ii][jj] = src[(long)(i0 + ii) * 256 + j0 + jj];
    }
    __syncthreads();
#pragma unroll
    for (int it = 0; it < 2; it++) {
        int s = t + it * 256;
        int jr = s >> 4, ip = s & 15;
        u32 lo; u32 hi = packsplit(T[ip * 2][jr], T[ip * 2 + 1][jr], lo);
        long idx = (long)bz * 32768 + (long)(j0 + jr) * 128 + (i0 >> 1) + ip;
        g_wcth[idx] = hi; g_wctl[idx] = lo;
    }
}

// ---------------------------------------------------------------------------
// kernB: 128 threads, 64x64 tile. Per (j-tile, x-tile, bz): K=i=256.
// ---------------------------------------------------------------------------
__global__ __launch_bounds__(128, 6)
void kernB_mma()
{
    __shared__ u32 AsH[8][PADS], AsL[8][PADS], WsH[8][PADS], WsL[8][PADS];
    int tid = threadIdx.x, lane = tid & 31, wid = tid >> 5;
    int j0 = blockIdx.x * 64, m0 = blockIdx.y * 64;
    int bz = blockIdx.z, b = bz >> 4, z = bz & 15;
    int wm = (wid & 1) * 32, wn = (wid >> 1) * 32;

    const u32* aH = g_sth + (long)b * 32768;
    const u32* aL = g_stl + (long)b * 32768;
    const u32* bH = g_wcth + (long)bz * 32768;
    const u32* bL = g_wctl + (long)bz * 32768;

    float acc[2][4][4];
#pragma unroll
    for (int mb = 0; mb < 2; mb++)
#pragma unroll
        for (int nb = 0; nb < 4; nb++)
#pragma unroll
            for (int q = 0; q < 4; q++) acc[mb][nb][q] = 0.f;

    int cm = tid >> 1, ckq = (tid & 1) * 4;    // 64 rows x 2 halves

    uint4 avh = *(const uint4*)(aH + (long)(m0 + cm) * 128 + ckq);
    uint4 avl = *(const uint4*)(aL + (long)(m0 + cm) * 128 + ckq);
    uint4 bvh = *(const uint4*)(bH + (long)(j0 + cm) * 128 + ckq);
    uint4 bvl = *(const uint4*)(bL + (long)(j0 + cm) * 128 + ckq);

    for (int c = 0; c < 16; c++) {
        AsH[ckq + 0][cm] = avh.x; AsH[ckq + 1][cm] = avh.y;
        AsH[ckq + 2][cm] = avh.z; AsH[ckq + 3][cm] = avh.w;
        AsL[ckq + 0][cm] = avl.x; AsL[ckq + 1][cm] = avl.y;
        AsL[ckq + 2][cm] = avl.z; AsL[ckq + 3][cm] = avl.w;
        WsH[ckq + 0][cm] = bvh.x; WsH[ckq + 1][cm] = bvh.y;
        WsH[ckq + 2][cm] = bvh.z; WsH[ckq + 3][cm] = bvh.w;
        WsL[ckq + 0][cm] = bvl.x; WsL[ckq + 1][cm] = bvl.y;
        WsL[ckq + 2][cm] = bvl.z; WsL[ckq + 3][cm] = bvl.w;
        __syncthreads();
        if (c + 1 < 16) {
            int k1 = (c + 1) * 8;
            avh = *(const uint4*)(aH + (long)(m0 + cm) * 128 + k1 + ckq);
            avl = *(const uint4*)(aL + (long)(m0 + cm) * 128 + k1 + ckq);
            bvh = *(const uint4*)(bH + (long)(j0 + cm) * 128 + k1 + ckq);
            bvl = *(const uint4*)(bL + (long)(j0 + cm) * 128 + k1 + ckq);
        }
        mma_phase64(AsH, AsL, WsH, WsL, lane, wm, wn, acc);
        __syncthreads();
    }

    int fr = lane >> 2, fc = (lane & 3) * 2;
#pragma unroll
    for (int mb = 0; mb < 2; mb++) {
#pragma unroll
        for (int nb = 0; nb < 4; nb++) {
            long x = m0 + wm + mb * 16 + fr;
            long jp = (j0 + wn + nb * 8 + fc) >> 1;
            long p0 = ((long)b * 4096 + x * 16 + z) * 128 + jp;
            long p1 = ((long)b * 4096 + (x + 8) * 16 + z) * 128 + jp;
            u32 lo; u32 hi = packsplit(acc[mb][nb][0], acc[mb][nb][1], lo);
            g_th[p0] = hi; g_tl[p0] = lo;
            hi = packsplit(acc[mb][nb][2], acc[mb][nb][3], lo);
            g_th[p1] = hi; g_tl[p1] = lo;
        }
    }
}

// ---------------------------------------------------------------------------
// kernC: 128 threads, 64x64 tile. Per (y-tile, m-tile, b): K=j=256.
// ---------------------------------------------------------------------------
__global__ __launch_bounds__(128, 6)
void kernC_mma(float* __restrict__ out)
{
    __shared__ u32 AsH[8][PADS], AsL[8][PADS], WsH[8][PADS], WsL[8][PADS];
    int tid = threadIdx.x, lane = tid & 31, wid = tid >> 5;
    int n0 = blockIdx.x * 64, m0 = blockIdx.y * 64;
    int b = blockIdx.z;
    int wm = (wid & 1) * 32, wn = (wid >> 1) * 32;

    const u32* aH = g_th + (long)b * 524288;
    const u32* aL = g_tl + (long)b * 524288;
    const u32* eH = g_endh + (long)b * 32768;
    const u32* eL = g_endl + (long)b * 32768;
    float* O = out + (long)b * 1048576;

    float acc[2][4][4];
#pragma unroll
    for (int mb = 0; mb < 2; mb++)
#pragma unroll
        for (int nb = 0; nb < 4; nb++)
#pragma unroll
            for (int q = 0; q < 4; q++) acc[mb][nb][q] = 0.f;

    int cm = tid >> 1, ckq = (tid & 1) * 4;

    uint4 avh = *(const uint4*)(aH + (long)(m0 + cm) * 128 + ckq);
    uint4 avl = *(const uint4*)(aL + (long)(m0 + cm) * 128 + ckq);
    uint4 evh = *(const uint4*)(eH + (long)(n0 + cm) * 128 + ckq);
    uint4 evl = *(const uint4*)(eL + (long)(n0 + cm) * 128 + ckq);

    for (int c = 0; c < 16; c++) {
        AsH[ckq + 0][cm] = avh.x; AsH[ckq + 1][cm] = avh.y;
        AsH[ckq + 2][cm] = avh.z; AsH[ckq + 3][cm] = avh.w;
        AsL[ckq + 0][cm] = avl.x; AsL[ckq + 1][cm] = avl.y;
        AsL[ckq + 2][cm] = avl.z; AsL[ckq + 3][cm] = avl.w;
        WsH[ckq + 0][cm] = evh.x; WsH[ckq + 1][cm] = evh.y;
        WsH[ckq + 2][cm] = evh.z; WsH[ckq + 3][cm] = evh.w;
        WsL[ckq + 0][cm] = evl.x; WsL[ckq + 1][cm] = evl.y;
        WsL[ckq + 2][cm] = evl.z; WsL[ckq + 3][cm] = evl.w;
        __syncthreads();
        if (c + 1 < 16) {
            int k1 = (c + 1) * 8;
            avh = *(const uint4*)(aH + (long)(m0 + cm) * 128 + k1 + ckq);
            avl = *(const uint4*)(aL + (long)(m0 + cm) * 128 + k1 + ckq);
            evh = *(const uint4*)(eH + (long)(n0 + cm) * 128 + k1 + ckq);
            evl = *(const uint4*)(eL + (long)(n0 + cm) * 128 + k1 + ckq);
        }
        mma_phase64(AsH, AsL, WsH, WsL, lane, wm, wn, acc);
        __syncthreads();
    }

    int fr = lane >> 2, fc = (lane & 3) * 2;
#pragma unroll
    for (int mb = 0; mb < 2; mb++) {
#pragma unroll
        for (int nb = 0; nb < 4; nb++) {
            int m  = m0 + wm + mb * 16 + fr;
            long y = n0 + wn + nb * 8 + fc;
            long x = m >> 4;  int zz = m & 15;
            O[x * 4096 + y * 16 + zz]       = acc[mb][nb][0];
            O[x * 4096 + (y + 1) * 16 + zz] = acc[mb][nb][1];
            int m2 = m + 8;
            long x2 = m2 >> 4; int z2 = m2 & 15;
            O[x2 * 4096 + y * 16 + z2]       = acc[mb][nb][2];
            O[x2 * 4096 + (y + 1) * 16 + z2] = acc[mb][nb][3];
        }
    }
}

// ===================== launch ================================================
extern "C" void kernel_launch(void* const* d_in, const int* in_sizes, int n_in,
                              void* d_out, int out_size)
{
    const float* start = (const float*)d_in[0];   // [8,256,256]
    const float* endl  = (const float*)d_in[1];   // [8,256,256]
    const float* cls   = (const float*)d_in[2];   // [8,16,256]
    const float* W     = (const float*)d_in[3];   // [256,256,256]
    float* out = (float*)d_out;                   // [8,256,256,16]

    split_inputs<<<2112, 256>>>(cls, start, endl);

    dim3 gA(2, 1, 256);      // j-half, -, i
    kernA_mma<<<gA, 256>>>(W);

    dim3 gR(8, 8, 128);      // j-tile, i-tile, bz
    repack_wc<<<gR, 256>>>();

    dim3 gB(4, 4, 128);      // j (64), x (64), bz
    kernB_mma<<<gB, 128>>>();

    dim3 gC(4, 64, 8);       // y (64), m (64), b
    kernC_mma<<<gC, 128>>>(out);
}

// round 17
// speedup vs baseline: 1.7380x; 1.7380x over previous
#include <cuda_runtime.h>
#include <cuda_fp16.h>
#include <cstdint>

// Problem: B=8, L=256, Z=16, H=256. Reassociated (12.9 GFLOP):
//   A: Wc[bz][i][j] = sum_o cls[bz][o] * W[i][o][j]
//   B: t[b][x*16+z][j] = sum_i start[b][x][i] * Wc[bz][i][j]
//   C: out[b][x][y][z] = sum_j t[b][m][j] * end[b][y][j]
// R17: fp16 mma.sync m16n8k16 with 2-TERM split (A = Ah+Al, B = Bh only):
//   D = Ah*Bh + Al*Bh = A*Bh;  dropped error A*Bl ~ 2^-12 RMS per stage.
// 33% less raw MMA work vs bf16 3-term (we are at the legacy-HMMA HW ceiling).

typedef unsigned u32;
typedef unsigned long long u64;

__device__ u32 g_clsh[16384],   g_clsl[16384];    // cls  [bz=128][op=128] hi+lo
__device__ u32 g_sth[262144],   g_stl[262144];    // start[b*x=2048][ip=128] hi+lo
__device__ u32 g_endh[262144];                    // end  [b*y=2048][jp=128] hi only
__device__ float g_wc[8388608];                   // Wc   [bz][i][j] fp32
__device__ u32 g_wcth[4194304];                   // Wc^T [bz][j=256][ip=128] hi only
__device__ u32 g_th[4194304],   g_tl[4194304];    // t    [b*m=32768][jp=128] hi+lo

// ---------------- fp16 helpers --------------------------------------------
__device__ __forceinline__ u32 packh2(float f0, float f1) {
    __half h0 = __float2half_rn(f0), h1 = __float2half_rn(f1);
    return ((u32)__half_as_ushort(h1) << 16) | (u32)__half_as_ushort(h0);
}
__device__ __forceinline__ u32 packsplit_h(float f0, float f1, u32& lo) {
    __half h0 = __float2half_rn(f0), h1 = __float2half_rn(f1);
    float r0 = f0 - __half2float(h0), r1 = f1 - __half2float(h1);
    lo = packh2(r0, r1);
    return ((u32)__half_as_ushort(h1) << 16) | (u32)__half_as_ushort(h0);
}
__device__ __forceinline__ void mma_f16(float d[4], u32 a0, u32 a1, u32 a2, u32 a3,
                                        u32 b0, u32 b1)
{
    asm("mma.sync.aligned.m16n8k16.row.col.f32.f16.f16.f32 "
        "{%0,%1,%2,%3}, {%4,%5,%6,%7}, {%8,%9}, {%0,%1,%2,%3};"
        : "+f"(d[0]), "+f"(d[1]), "+f"(d[2]), "+f"(d[3])
        : "r"(a0), "r"(a1), "r"(a2), "r"(a3), "r"(b0), "r"(b1));
}

#define PAD 136   // (8*kp + col) % 32 distinct per lane group -> conflict-free

// One k=16 chunk: 2-term, 32 MMAs. A hi+lo, B hi only.
__device__ __forceinline__ void mma_phase(const u32 (*AsH)[PAD], const u32 (*AsL)[PAD],
                                          const u32 (*WsH)[PAD],
                                          int lane, int wm, int wn, float acc[2][8][4])
{
    int fr = lane >> 2, fk = lane & 3;
    u32 ah[2][4], al[2][4];
#pragma unroll
    for (int mb = 0; mb < 2; mb++) {
        int m = wm + mb * 16 + fr;
        ah[mb][0] = AsH[fk][m];     ah[mb][1] = AsH[fk][m + 8];
        ah[mb][2] = AsH[fk + 4][m]; ah[mb][3] = AsH[fk + 4][m + 8];
        al[mb][0] = AsL[fk][m];     al[mb][1] = AsL[fk][m + 8];
        al[mb][2] = AsL[fk + 4][m]; al[mb][3] = AsL[fk + 4][m + 8];
    }
#pragma unroll
    for (int g = 0; g < 2; g++) {
        u32 bh0[4], bh1[4];
#pragma unroll
        for (int q = 0; q < 4; q++) {
            int n = wn + (g * 4 + q) * 8 + fr;
            bh0[q] = WsH[fk][n]; bh1[q] = WsH[fk + 4][n];
        }
#pragma unroll
        for (int q = 0; q < 4; q++)
#pragma unroll
            for (int mb = 0; mb < 2; mb++)
                mma_f16(acc[mb][g * 4 + q], ah[mb][0], ah[mb][1], ah[mb][2], ah[mb][3],
                        bh0[q], bh1[q]);
#pragma unroll
        for (int q = 0; q < 4; q++)
#pragma unroll
            for (int mb = 0; mb < 2; mb++)
                mma_f16(acc[mb][g * 4 + q], al[mb][0], al[mb][1], al[mb][2], al[mb][3],
                        bh0[q], bh1[q]);
    }
}

// --------------------------- input split prepass ---------------------------
// cls: hi+lo. start: hi+lo. end: hi only.
__global__ void split_inputs(const float* __restrict__ cls,
                             const float* __restrict__ start,
                             const float* __restrict__ endl)
{
    long p = (long)blockIdx.x * 256 + threadIdx.x;
    if (p < 16384) {
        float f0 = cls[p * 2], f1 = cls[p * 2 + 1];
        u32 lo; g_clsh[p] = packsplit_h(f0, f1, lo); g_clsl[p] = lo;
    } else if (p < 16384 + 262144) {
        long off = p - 16384;
        float f0 = start[off * 2], f1 = start[off * 2 + 1];
        u32 lo; g_sth[off] = packsplit_h(f0, f1, lo); g_stl[off] = lo;
    } else if (p < 16384 + 524288) {
        long off = p - 16384 - 262144;
        g_endh[off] = packh2(endl[off * 2], endl[off * 2 + 1]);
    }
}

// ---------------------------------------------------------------------------
// kernA: per (j-half, i): Wc[bz=128][j=128] over K=o=256 (16 chunks of k16).
// A = cls (hi+lo). B = W fp32, converted to fp16-hi in-kernel. Single buf.
// ---------------------------------------------------------------------------
__global__ __launch_bounds__(256, 2)
void kernA_mma(const float* __restrict__ W)
{
    __shared__ u32 AsH[8][PAD], AsL[8][PAD], WsH[8][PAD];
    int tid = threadIdx.x, lane = tid & 31, wid = tid >> 5;
    int j0 = blockIdx.x * 128, i_dim = blockIdx.z;
    int wm = (wid & 3) * 32, wn = (wid >> 2) * 64;
    const float* Wi = W + (long)i_dim * 65536;   // [o=256][j=256]

    float acc[2][8][4];
#pragma unroll
    for (int mb = 0; mb < 2; mb++)
#pragma unroll
        for (int nb = 0; nb < 8; nb++)
#pragma unroll
            for (int q = 0; q < 4; q++) acc[mb][nb][q] = 0.f;

    int kp = tid >> 5;            // 0..7: o-pair row within chunk
    int j4 = (tid & 31) * 4;      // 4 j columns
    int cm = tid >> 1, ckq = (tid & 1) * 4;

    float4 w0 = *(const float4*)(Wi + (long)(2 * kp) * 256 + j0 + j4);
    float4 w1 = *(const float4*)(Wi + (long)(2 * kp + 1) * 256 + j0 + j4);
    uint4 vh = *(const uint4*)(g_clsh + (long)cm * 128 + ckq);
    uint4 vl = *(const uint4*)(g_clsl + (long)cm * 128 + ckq);

    for (int c = 0; c < 16; c++) {
        {
            *(uint4*)&WsH[kp][j4] = make_uint4(
                packh2(w0.x, w1.x), packh2(w0.y, w1.y),
                packh2(w0.z, w1.z), packh2(w0.w, w1.w));
            AsH[ckq + 0][cm] = vh.x; AsH[ckq + 1][cm] = vh.y;
            AsH[ckq + 2][cm] = vh.z; AsH[ckq + 3][cm] = vh.w;
            AsL[ckq + 0][cm] = vl.x; AsL[ckq + 1][cm] = vl.y;
            AsL[ckq + 2][cm] = vl.z; AsL[ckq + 3][cm] = vl.w;
        }
        __syncthreads();
        if (c + 1 < 16) {
            int o1 = (c + 1) * 16, kp1 = (c + 1) * 8;
            w0 = *(const float4*)(Wi + (long)(o1 + 2 * kp) * 256 + j0 + j4);
            w1 = *(const float4*)(Wi + (long)(o1 + 2 * kp + 1) * 256 + j0 + j4);
            vh = *(const uint4*)(g_clsh + (long)cm * 128 + kp1 + ckq);
            vl = *(const uint4*)(g_clsl + (long)cm * 128 + kp1 + ckq);
        }
        mma_phase(AsH, AsL, WsH, lane, wm, wn, acc);
        __syncthreads();
    }

    int fr = lane >> 2, fc = (lane & 3) * 2;
#pragma unroll
    for (int mb = 0; mb < 2; mb++) {
#pragma unroll
        for (int nb = 0; nb < 8; nb++) {
            long m = wm + mb * 16 + fr;
            long j = j0 + wn + nb * 8 + fc;
            float* p0 = g_wc + m * 65536 + (long)i_dim * 256 + j;
            float* p1 = p0 + 8 * 65536;
            *(float2*)p0 = make_float2(acc[mb][nb][0], acc[mb][nb][1]);
            *(float2*)p1 = make_float2(acc[mb][nb][2], acc[mb][nb][3]);
        }
    }
}

// ---------------------------------------------------------------------------
// repack: Wc fp32 [bz][i][j] -> Wc^T fp16-hi pairs [bz][j][ip=128].
// ---------------------------------------------------------------------------
__global__ void repack_wc()
{
    __shared__ float T[32][33];
    int bz = blockIdx.z, i0 = blockIdx.y * 32, j0 = blockIdx.x * 32;
    const float* src = g_wc + (long)bz * 65536;
    int t = threadIdx.x;
    int jj = t & 31, g = t >> 5;
#pragma unroll
    for (int rr = 0; rr < 4; rr++) {
        int ii = g * 4 + rr;
        T[ii][jj] = src[(long)(i0 + ii) * 256 + j0 + jj];
    }
    __syncthreads();
#pragma unroll
    for (int it = 0; it < 2; it++) {
        int s = t + it * 256;
        int jr = s >> 4, ip = s & 15;
        long idx = (long)bz * 32768 + (long)(j0 + jr) * 128 + (i0 >> 1) + ip;
        g_wcth[idx] = packh2(T[ip * 2][jr], T[ip * 2 + 1][jr]);
    }
}

// ---------------------------------------------------------------------------
// kernB: per bz: D[x=128][j=128] over K=i=256 (16 chunks). Single buf.
// A = start (hi+lo). B = Wc^T (hi only).
// ---------------------------------------------------------------------------
__global__ __launch_bounds__(256, 2)
void kernB_mma()
{
    __shared__ u32 AsH[8][PAD], AsL[8][PAD], WsH[8][PAD];
    int tid = threadIdx.x, lane = tid & 31, wid = tid >> 5;
    int j0 = blockIdx.x * 128, m0 = blockIdx.y * 128;
    int bz = blockIdx.z, b = bz >> 4, z = bz & 15;
    int wm = (wid & 3) * 32, wn = (wid >> 2) * 64;

    const u32* aH = g_sth + (long)b * 32768;
    const u32* aL = g_stl + (long)b * 32768;
    const u32* bH = g_wcth + (long)bz * 32768;

    float acc[2][8][4];
#pragma unroll
    for (int mb = 0; mb < 2; mb++)
#pragma unroll
        for (int nb = 0; nb < 8; nb++)
#pragma unroll
            for (int q = 0; q < 4; q++) acc[mb][nb][q] = 0.f;

    int cm = tid >> 1, ckq = (tid & 1) * 4;

    uint4 avh = *(const uint4*)(aH + (long)(m0 + cm) * 128 + ckq);
    uint4 avl = *(const uint4*)(aL + (long)(m0 + cm) * 128 + ckq);
    uint4 bvh = *(const uint4*)(bH + (long)(j0 + cm) * 128 + ckq);

    for (int c = 0; c < 16; c++) {
        AsH[ckq + 0][cm] = avh.x; AsH[ckq + 1][cm] = avh.y;
        AsH[ckq + 2][cm] = avh.z; AsH[ckq + 3][cm] = avh.w;
        AsL[ckq + 0][cm] = avl.x; AsL[ckq + 1][cm] = avl.y;
        AsL[ckq + 2][cm] = avl.z; AsL[ckq + 3][cm] = avl.w;
        WsH[ckq + 0][cm] = bvh.x; WsH[ckq + 1][cm] = bvh.y;
        WsH[ckq + 2][cm] = bvh.z; WsH[ckq + 3][cm] = bvh.w;
        __syncthreads();
        if (c + 1 < 16) {
            int k1 = (c + 1) * 8;
            avh = *(const uint4*)(aH + (long)(m0 + cm) * 128 + k1 + ckq);
            avl = *(const uint4*)(aL + (long)(m0 + cm) * 128 + k1 + ckq);
            bvh = *(const uint4*)(bH + (long)(j0 + cm) * 128 + k1 + ckq);
        }
        mma_phase(AsH, AsL, WsH, lane, wm, wn, acc);
        __syncthreads();
    }

    int fr = lane >> 2, fc = (lane & 3) * 2;
#pragma unroll
    for (int mb = 0; mb < 2; mb++) {
#pragma unroll
        for (int nb = 0; nb < 8; nb++) {
            long x = m0 + wm + mb * 16 + fr;
            long jp = (j0 + wn + nb * 8 + fc) >> 1;
            long p0 = ((long)b * 4096 + x * 16 + z) * 128 + jp;
            long p1 = ((long)b * 4096 + (x + 8) * 16 + z) * 128 + jp;
            u32 lo; u32 hi = packsplit_h(acc[mb][nb][0], acc[mb][nb][1], lo);
            g_th[p0] = hi; g_tl[p0] = lo;
            hi = packsplit_h(acc[mb][nb][2], acc[mb][nb][3], lo);
            g_th[p1] = hi; g_tl[p1] = lo;
        }
    }
}

// ---------------------------------------------------------------------------
// kernC: per b: D[m=128][y=128] over K=j=256 (16 chunks). Single buf.
// A = t (hi+lo). B = end (hi only). Output fp32 out[b][x][y][z].
// ---------------------------------------------------------------------------
__global__ __launch_bounds__(256, 2)
void kernC_mma(float* __restrict__ out)
{
    __shared__ u32 AsH[8][PAD], AsL[8][PAD], WsH[8][PAD];
    int tid = threadIdx.x, lane = tid & 31, wid = tid >> 5;
    int n0 = blockIdx.x * 128, m0 = blockIdx.y * 128;
    int b = blockIdx.z;
    int wm = (wid & 3) * 32, wn = (wid >> 2) * 64;

    const u32* aH = g_th + (long)b * 524288;
    const u32* aL = g_tl + (long)b * 524288;
    const u32* eH = g_endh + (long)b * 32768;
    float* O = out + (long)b * 1048576;

    float acc[2][8][4];
#pragma unroll
    for (int mb = 0; mb < 2; mb++)
#pragma unroll
        for (int nb = 0; nb < 8; nb++)
#pragma unroll
            for (int q = 0; q < 4; q++) acc[mb][nb][q] = 0.f;

    int cm = tid >> 1, ckq = (tid & 1) * 4;

    uint4 avh = *(const uint4*)(aH + (long)(m0 + cm) * 128 + ckq);
    uint4 avl = *(const uint4*)(aL + (long)(m0 + cm) * 128 + ckq);
    uint4 evh = *(const uint4*)(eH + (long)(n0 + cm) * 128 + ckq);

    for (int c = 0; c < 16; c++) {
        AsH[ckq + 0][cm] = avh.x; AsH[ckq + 1][cm] = avh.y;
        AsH[ckq + 2][cm] = avh.z; AsH[ckq + 3][cm] = avh.w;
        AsL[ckq + 0][cm] = avl.x; AsL[ckq + 1][cm] = avl.y;
        AsL[ckq + 2][cm] = avl.z; AsL[ckq + 3][cm] = avl.w;
        WsH[ckq + 0][cm] = evh.x; WsH[ckq + 1][cm] = evh.y;
        WsH[ckq + 2][cm] = evh.z; WsH[ckq + 3][cm] = evh.w;
        __syncthreads();
        if (c + 1 < 16) {
            int k1 = (c + 1) * 8;
            avh = *(const uint4*)(aH + (long)(m0 + cm) * 128 + k1 + ckq);
            avl = *(const uint4*)(aL + (long)(m0 + cm) * 128 + k1 + ckq);
            evh = *(const uint4*)(eH + (long)(n0 + cm) * 128 + k1 + ckq);
        }
        mma_phase(AsH, AsL, WsH, lane, wm, wn, acc);
        __syncthreads();
    }

    int fr = lane >> 2, fc = (lane & 3) * 2;
#pragma unroll
    for (int mb = 0; mb < 2; mb++) {
#pragma unroll
        for (int nb = 0; nb < 8; nb++) {
            int m  = m0 + wm + mb * 16 + fr;
            long y = n0 + wn + nb * 8 + fc;
            long x = m >> 4;  int zz = m & 15;
            O[x * 4096 + y * 16 + zz]       = acc[mb][nb][0];
            O[x * 4096 + (y + 1) * 16 + zz] = acc[mb][nb][1];
            int m2 = m + 8;
            long x2 = m2 >> 4; int z2 = m2 & 15;
            O[x2 * 4096 + y * 16 + z2]       = acc[mb][nb][2];
            O[x2 * 4096 + (y + 1) * 16 + z2] = acc[mb][nb][3];
        }
    }
}

// ===================== launch ================================================
extern "C" void kernel_launch(void* const* d_in, const int* in_sizes, int n_in,
                              void* d_out, int out_size)
{
    const float* start = (const float*)d_in[0];   // [8,256,256]
    const float* endl  = (const float*)d_in[1];   // [8,256,256]
    const float* cls   = (const float*)d_in[2];   // [8,16,256]
    const float* W     = (const float*)d_in[3];   // [256,256,256]
    float* out = (float*)d_out;                   // [8,256,256,16]

    split_inputs<<<2112, 256>>>(cls, start, endl);

    dim3 gA(2, 1, 256);      // j-half, -, i
    kernA_mma<<<gA, 256>>>(W);

    dim3 gR(8, 8, 128);      // j-tile, i-tile, bz
    repack_wc<<<gR, 256>>>();

    dim3 gB(2, 2, 128);      // j, x, bz
    kernB_mma<<<gB, 256>>>();

    dim3 gC(2, 32, 8);       // y, m, b
    kernC_mma<<<gC, 256>>>(out);
}